// round 13
// baseline (speedup 1.0000x reference)
#include <cuda_runtime.h>
#include <cuda_fp16.h>
#include <math_constants.h>
#include <cstdint>

#define NUM_E 8192
#define DIM   512
#define BATCH 8
#define LSEQ  4096
#define NTOK  (BATCH * LSEQ)          // 32768
#define QELEMS ((size_t)BATCH * DIM * LSEQ)  // 16777216
#define CAP   256
#define TAU   8e-4f
#define CSCALE 8192.0f
#define NEG2S (-2.0f / 8192.0f)

// ---------------- scratch (device globals; no runtime allocation) ----------
__device__ __align__(256) float   g_xT[(size_t)NTOK * DIM];
__device__ __align__(256) __half  g_xhf[(size_t)NTOK * DIM];       // [N,D] fp16
__device__ __align__(256) float   g_codebook[(size_t)NUM_E * DIM];
__device__ __align__(256) __half2 g_chfT2[(size_t)DIM * NUM_E];    // [D,K] splat fp16*8192
__device__ float    g_xnorm[NTOK];
__device__ float    g_cnorm[NUM_E];
__device__ int      g_ck[(size_t)NTOK * CAP];    // candidate indices
__device__ float    g_cv[(size_t)NTOK * CAP];    // candidate fp16-filter scores
__device__ uint32_t g_fminu[NTOK];               // global fp16 min (fmap'd uint)
__device__ uint32_t g_cnt[NTOK];
__device__ int      g_argmin[NTOK];
__device__ double   g_loss;

// order-preserving float<->uint map for unsigned atomicMin
__device__ __forceinline__ uint32_t fmap(float f) {
    uint32_t u = __float_as_uint(f);
    return (u & 0x80000000u) ? ~u : (u | 0x80000000u);
}
__device__ __forceinline__ float funmap(uint32_t u) {
    return __uint_as_float((u & 0x80000000u) ? (u & 0x7FFFFFFFu) : ~u);
}
__device__ __forceinline__ uint32_t smem_u32(const void* p) {
    uint32_t a;
    asm("{ .reg .u64 t; cvta.to.shared.u64 t, %1; cvt.u32.u64 %0, t; }"
        : "=r"(a) : "l"(p));
    return a;
}
__device__ __forceinline__ void cp16(uint32_t dst, const void* src) {
    asm volatile("cp.async.cg.shared.global [%0], [%1], 16;" :: "r"(dst), "l"(src));
}
#define CP_COMMIT() asm volatile("cp.async.commit_group;" ::: "memory")
#define CP_WAIT0()  asm volatile("cp.async.wait_group 0;" ::: "memory")

// ---------------------------------------------------------------------------
// inputs [B, D, L] -> g_xT / g_xhf [(b*L + l), d]; first 128 blocks also init
// the filter-side scratch (g_cnt / g_fminu / g_loss), consumed only later.
__global__ void transpose_kernel(const float* __restrict__ in) {
    __shared__ float tile[32][33];
    int b  = blockIdx.z;
    int d0 = blockIdx.y * 32;
    int l0 = blockIdx.x * 32;
    int tx = threadIdx.x, ty = threadIdx.y;
    int tid = ty * 32 + tx;
    int gid = (blockIdx.z * gridDim.y + blockIdx.y) * gridDim.x + blockIdx.x;
    if (gid < NTOK / 256) {
        int i = gid * 256 + tid;
        g_cnt[i] = 0u;
        g_fminu[i] = 0xFF800000u;   // fmap(+inf)
        if (i == 0) g_loss = 0.0;
    }
    const float* src = in + (size_t)b * DIM * LSEQ;
#pragma unroll
    for (int i = 0; i < 4; i++)
        tile[ty + i * 8][tx] = src[(size_t)(d0 + ty + i * 8) * LSEQ + l0 + tx];
    __syncthreads();
#pragma unroll
    for (int i = 0; i < 4; i++) {
        int l = l0 + ty + i * 8;
        float v = tile[tx][ty + i * 8];
        size_t idx = (size_t)(b * LSEQ + l) * DIM + d0 + tx;
        g_xT[idx] = v;
        g_xhf[idx] = __float2half(v);
    }
}

// codebook[k][d] = sum_j emb[k][j] * proj[d][j]  (128x128 tile, 8x8/thread)
// also writes transposed scaled SPLATTED fp16 copy g_chfT2[d][k] = (v,v)
__global__ __launch_bounds__(256, 2) void codebook_gemm_kernel(
    const float* __restrict__ E, const float* __restrict__ P) {
    __shared__ float As[8][128];
    __shared__ float Bs[8][128];
    int tid = threadIdx.x;
    int ty = tid >> 4, tx = tid & 15;
    int k0 = blockIdx.y * 128;
    int d0 = blockIdx.x * 128;
    int srow = tid >> 2;
    int scol = (tid & 3) * 2;
    float acc[8][8];
#pragma unroll
    for (int i = 0; i < 8; i++)
#pragma unroll
        for (int j = 0; j < 8; j++) acc[i][j] = 0.f;

    for (int j0 = 0; j0 < DIM; j0 += 8) {
#pragma unroll
        for (int i = 0; i < 2; i++) {
            int m = srow + i * 64;
            float2 av = *(const float2*)&E[(size_t)(k0 + m) * DIM + j0 + scol];
            float2 bv = *(const float2*)&P[(size_t)(d0 + m) * DIM + j0 + scol];
            As[scol][m] = av.x; As[scol + 1][m] = av.y;
            Bs[scol][m] = bv.x; Bs[scol + 1][m] = bv.y;
        }
        __syncthreads();
#pragma unroll
        for (int j = 0; j < 8; j++) {
            float a[8], bb[8];
#pragma unroll
            for (int i = 0; i < 8; i++) a[i]  = As[j][ty * 8 + i];
#pragma unroll
            for (int i = 0; i < 8; i++) bb[i] = Bs[j][tx * 8 + i];
#pragma unroll
            for (int i = 0; i < 8; i++)
#pragma unroll
                for (int jj = 0; jj < 8; jj++) acc[i][jj] += a[i] * bb[jj];
        }
        __syncthreads();
    }
#pragma unroll
    for (int i = 0; i < 8; i++)
#pragma unroll
        for (int jj = 0; jj < 8; jj++)
            g_codebook[(size_t)(k0 + ty * 8 + i) * DIM + d0 + tx * 8 + jj] = acc[i][jj];
    // splatted fp16: g_chfT2[d][k] = half2(v, v), 8 consecutive k per row write
#pragma unroll
    for (int jj = 0; jj < 8; jj++) {
        __half2 w[8];
#pragma unroll
        for (int i = 0; i < 8; i++)
            w[i] = __half2half2(__float2half(acc[i][jj] * CSCALE));
        __half2* dst = &g_chfT2[(size_t)(d0 + tx * 8 + jj) * NUM_E + k0 + ty * 8];
        *(uint4*)(dst)     = *(uint4*)&w[0];
        *(uint4*)(dst + 4) = *(uint4*)&w[4];
    }
}

// merged: warps [0, NTOK) -> xnorm rows; warps [NTOK, NTOK+NUM_E) -> cnorm rows
__global__ void rownorm_all_kernel() {
    int warp = (blockIdx.x * blockDim.x + threadIdx.x) >> 5;
    int lane = threadIdx.x & 31;
    if (warp >= NTOK + NUM_E) return;
    bool isc = warp >= NTOK;
    const float* r = isc ? (g_codebook + (size_t)(warp - NTOK) * DIM)
                         : (g_xT + (size_t)warp * DIM);
    float s = 0.f;
#pragma unroll
    for (int i = 0; i < DIM / 32; i++) { float v = r[lane + i * 32]; s += v * v; }
#pragma unroll
    for (int o = 16; o; o >>= 1) s += __shfl_down_sync(0xffffffffu, s, o);
    if (lane == 0) {
        if (isc) g_cnorm[warp - NTOK] = s;
        else     g_xnorm[warp] = s;
    }
}

// ------------------- fp16x2 (HFMA2) candidate-filter kernel ----------------
// 512 threads/CTA (4 warps/SMSP for LDS-latency hiding).  K-SPLIT grid:
// blockIdx.x = m_tile * 8 + k_eighth.  Each CTA: 128 tokens x 1024 codes.
// Thread grid 32x16: thread = 2 token-pairs (4 tokens) x 8 codes, acc[2][8].
// Codes staged via cp.async in pairs of 32-dim chunks, 4-buffer ring.
#define OFF_X    0                    // Xp2 [512][64] half2 = 131072
#define OFF_C    131072               // Cs [4][32][128] half2 = 65536
#define OFF_RMIN 196608               // 512
#define OFF_CNS  197120               // 512
#define OFF_THR  197632               // 512
#define SMEM_REQ 198144

__global__ __launch_bounds__(512, 1) void filter_kernel() {
    extern __shared__ __align__(16) char sm[];
    uint32_t smb = smem_u32(sm);
    int tid = threadIdx.x;
    int m0 = (blockIdx.x >> 3) * 128;
    int e8 = blockIdx.x & 7;           // k-eighth: codes [e8*1024, e8*1024+1024)
    int ty = tid >> 4, tx = tid & 15;  // ty 0..31: 2 token-pairs; tx: 8 codes

    __half2*  Xp2    = (__half2*)(sm + OFF_X);     // [512][64]
    uint32_t  csmem  = smb + OFF_C;                // ring base (bytes)
    uint32_t* rmin_s = (uint32_t*)(sm + OFF_RMIN);
    float*    cn_s   = (float*)(sm + OFF_CNS);
    float*    thr_s  = (float*)(sm + OFF_THR);

    if (tid < 128) rmin_s[tid] = 0xFF800000u;      // fmap(+inf)

    // ---- build resident Xp2[d][tp] = (x[2tp][d], x[2tp+1][d]) ----
    {
        int tp = tid & 63;
        int dh = (tid >> 6) * 64;    // 8 groups x 64 dims
        const uint4* x0 = (const uint4*)(g_xhf + (size_t)(m0 + 2 * tp) * DIM + dh);
        const uint4* x1 = (const uint4*)(g_xhf + (size_t)(m0 + 2 * tp + 1) * DIM + dh);
#pragma unroll 4
        for (int v = 0; v < 8; v++) {
            uint4 q0 = x0[v];
            uint4 q1 = x1[v];
            const __half* h0 = (const __half*)&q0;
            const __half* h1 = (const __half*)&q1;
#pragma unroll
            for (int u = 0; u < 8; u++)
                Xp2[(size_t)(dh + v * 8 + u) * 64 + tp] = __halves2half2(h0[u], h1[u]);
        }
    }

    __half2 acc[2][8];
    const __half2 hz = __float2half2_rn(0.f);
#pragma unroll
    for (int i = 0; i < 2; i++)
#pragma unroll
        for (int p = 0; p < 8; p++) acc[i][p] = hz;

    // cp.async staging: 512 threads, 2 units each
    int crow = tid >> 4;               // 0..31 (dim within chunk)
    int uu   = tid & 15;               // unit group: units uu, uu+16
    auto issue_pair = [&](int tp) {
        if (tp < 64) {
#pragma unroll
            for (int h = 0; h < 2; h++) {
                int t = 2 * tp + h;
                int buf = (tp & 1) * 2 + h;
                const __half2* srow = g_chfT2
                    + (size_t)((t & 15) * 32 + crow) * NUM_E
                    + (e8 * 8 + (t >> 4)) * 128;
                uint32_t drow = csmem + (uint32_t)buf * 16384 + (uint32_t)crow * 512;
#pragma unroll
                for (int i = 0; i < 2; i++) {
                    int u = uu + i * 16;                      // logical 16B unit
                    uint32_t phys = (uint32_t)(((u & 1) << 4) + (u >> 1)) * 16;
                    cp16(drow + phys, srow + u * 4);
                }
            }
        }
        CP_COMMIT();
    };

    // compute one 32-dim chunk t from ring buffer buf
    auto compute_chunk = [&](int t, int buf) {
        int c = t & 15;
        const __half2* xb = Xp2 + (size_t)(c * 32) * 64 + ty * 2;
        const char* cbp = (const char*)sm + OFF_C + buf * 16384 + tx * 16;
#pragma unroll 8
        for (int j = 0; j < 32; j++) {
            uint2 xq = *(const uint2*)(xb + (size_t)j * 64);
            __half2 xv[2];
            xv[0] = *(__half2*)&xq.x; xv[1] = *(__half2*)&xq.y;
            uint4 cq0 = *(const uint4*)(cbp + j * 512);        // codes 8tx..+3
            uint4 cq1 = *(const uint4*)(cbp + j * 512 + 256);  // codes 8tx+4..+7
            __half2 cv[8];
            cv[0] = *(__half2*)&cq0.x; cv[1] = *(__half2*)&cq0.y;
            cv[2] = *(__half2*)&cq0.z; cv[3] = *(__half2*)&cq0.w;
            cv[4] = *(__half2*)&cq1.x; cv[5] = *(__half2*)&cq1.y;
            cv[6] = *(__half2*)&cq1.z; cv[7] = *(__half2*)&cq1.w;
#pragma unroll
            for (int i = 0; i < 2; i++)
#pragma unroll
                for (int p = 0; p < 8; p++)
                    acc[i][p] = __hfma2(xv[i], cv[p], acc[i][p]);
        }
    };

    issue_pair(0);

    for (int tp = 0; tp < 64; tp++) {  // 64 pairs = 8 tiles x 8 pairs
        CP_WAIT0();                    // pair tp landed
        __syncthreads();               // all reads of opposite buffer set done
        issue_pair(tp + 1);            // fill opposite set
        if ((tp & 7) == 0 && tid < 128)
            cn_s[tid] = __ldg(&g_cnorm[(e8 * 8 + (tp >> 3)) * 128 + tid]);

        compute_chunk(2 * tp,     (tp & 1) * 2);
        compute_chunk(2 * tp + 1, (tp & 1) * 2 + 1);

        if ((tp & 7) == 7) {
            int k0 = (e8 * 8 + (tp >> 3)) * 128;
            // ---- Phase A: per-token TILE min into rmin_s ----
#pragma unroll
            for (int i = 0; i < 2; i++) {
                float lm0 = CUDART_INF_F, lm1 = CUDART_INF_F;
#pragma unroll
                for (int p = 0; p < 8; p++) {
                    float2 f = __half22float2(acc[i][p]);
                    float cn = cn_s[tx * 8 + p];
                    lm0 = fminf(lm0, fmaf(f.x, NEG2S, cn));
                    lm1 = fminf(lm1, fmaf(f.y, NEG2S, cn));
                }
                atomicMin(&rmin_s[ty * 4 + 2 * i],     fmap(lm0));
                atomicMin(&rmin_s[ty * 4 + 2 * i + 1], fmap(lm1));
            }
            __syncthreads();
            // ---- merge tile min into GLOBAL min; threshold = merged + TAU
            if (tid < 128) {
                uint32_t tm  = rmin_s[tid];
                uint32_t old = atomicMin(&g_fminu[m0 + tid], tm);
                thr_s[tid] = funmap(old < tm ? old : tm) + TAU;
                rmin_s[tid] = 0xFF800000u;   // reset for next tile
            }
            __syncthreads();
            // ---- Phase B: append (k, sv) to GLOBAL within threshold ----
#pragma unroll
            for (int i = 0; i < 2; i++) {
                int r0 = ty * 4 + 2 * i, r1 = r0 + 1;
                float thr0 = thr_s[r0];
                float thr1 = thr_s[r1];
#pragma unroll
                for (int p = 0; p < 8; p++) {
                    float2 f = __half22float2(acc[i][p]);
                    float cn = cn_s[tx * 8 + p];
                    float s0 = fmaf(f.x, NEG2S, cn);
                    float s1 = fmaf(f.y, NEG2S, cn);
                    int kk = k0 + tx * 8 + p;
                    if (s0 <= thr0) {
                        uint32_t slot = atomicAdd(&g_cnt[m0 + r0], 1u);
                        if (slot < CAP) {
                            g_ck[(size_t)(m0 + r0) * CAP + slot] = kk;
                            g_cv[(size_t)(m0 + r0) * CAP + slot] = s0;
                        }
                    }
                    if (s1 <= thr1) {
                        uint32_t slot = atomicAdd(&g_cnt[m0 + r1], 1u);
                        if (slot < CAP) {
                            g_ck[(size_t)(m0 + r1) * CAP + slot] = kk;
                            g_cv[(size_t)(m0 + r1) * CAP + slot] = s1;
                        }
                    }
                    acc[i][p] = hz;
                }
            }
        }
    }
}

// exact fp32 rescore; pre-filter candidates by final global-min window.
// count > CAP => full-scan fallback (P ~ 0 with CAP=256)
__global__ __launch_bounds__(256) void rescore_kernel() {
    int t = blockIdx.x * 256 + threadIdx.x;
    float xn = g_xnorm[t];
    uint32_t n = g_cnt[t];
    float thr = funmap(g_fminu[t]) + TAU;
    const float4* xr = (const float4*)(g_xT + (size_t)t * DIM);
    float best = CUDART_INF_F;
    int bi = 0;
    bool fb = (n > CAP);
    int total = fb ? NUM_E : (int)n;
    for (int i = 0; i < total; i++) {
        int k;
        if (fb) {
            k = i;
        } else {
            if (g_cv[(size_t)t * CAP + i] > thr) continue;  // outside final window
            k = g_ck[(size_t)t * CAP + i];
        }
        const float4* cr = (const float4*)(g_codebook + (size_t)k * DIM);
        float acc = 0.f;
#pragma unroll 8
        for (int v = 0; v < DIM / 4; v++) {
            float4 a = xr[v], b = cr[v];
            acc = fmaf(a.x, b.x, acc);
            acc = fmaf(a.y, b.y, acc);
            acc = fmaf(a.z, b.z, acc);
            acc = fmaf(a.w, b.w, acc);
        }
        float dv = (xn + g_cnorm[k]) - 2.0f * acc;
        if (dv < best || (dv == best && k < bi)) { best = dv; bi = k; }
    }
    g_argmin[t] = bi;
}

// gather codebook rows, write quantized [B,D,L], indices-as-float, loss accum
__global__ __launch_bounds__(256) void gather_out_kernel(
    const float* __restrict__ in, float* __restrict__ out) {
    __shared__ float qs[16][513];
    __shared__ int sidx[16];
    __shared__ double wsum[8];
    int t0 = blockIdx.x * 16;
    int tid = threadIdx.x;
    if (tid < 16) sidx[tid] = g_argmin[t0 + tid];
    __syncthreads();
#pragma unroll
    for (int i = 0; i < 8; i++) {
        int e = tid + i * 256;
        int tok = e >> 7, d4 = e & 127;
        float4 v = *(const float4*)&g_codebook[(size_t)sidx[tok] * DIM + d4 * 4];
        qs[tok][d4 * 4]     = v.x;
        qs[tok][d4 * 4 + 1] = v.y;
        qs[tok][d4 * 4 + 2] = v.z;
        qs[tok][d4 * 4 + 3] = v.w;
    }
    __syncthreads();
    int b  = t0 / LSEQ;
    int l0 = t0 % LSEQ;
    const float* src = in  + (size_t)b * DIM * LSEQ;
    float*       dst = out + (size_t)b * DIM * LSEQ;
    double ls = 0.0;
#pragma unroll
    for (int i = 0; i < 32; i++) {
        int e = tid + i * 256;
        int d = e >> 4, l = e & 15;
        float q = qs[l][d];
        float x = src[(size_t)d * LSEQ + l0 + l];
        float dd = q - x;
        dst[(size_t)d * LSEQ + l0 + l] = x + dd;
        ls += (double)dd * (double)dd;
    }
    if (tid < 16) out[QELEMS + 1 + (size_t)(t0 + tid)] = (float)sidx[tid];
#pragma unroll
    for (int o = 16; o; o >>= 1) ls += __shfl_down_sync(0xffffffffu, ls, o);
    if ((tid & 31) == 0) wsum[tid >> 5] = ls;
    __syncthreads();
    if (tid == 0) {
        double s = 0.0;
#pragma unroll
        for (int w = 0; w < 8; w++) s += wsum[w];
        atomicAdd(&g_loss, s);
    }
}

__global__ void loss_final_kernel(float* __restrict__ out) {
    out[QELEMS] = (float)(1.25 * g_loss / (double)QELEMS);
}

// ---------------------------------------------------------------------------
extern "C" void kernel_launch(void* const* d_in, const int* in_sizes, int n_in,
                              void* d_out, int out_size) {
    const float* inputs = (const float*)d_in[0];
    const float* emb    = (const float*)d_in[1];
    const float* proj   = (const float*)d_in[2];
    float* out = (float*)d_out;

    static bool attr_done = false;
    if (!attr_done) {
        cudaFuncSetAttribute(filter_kernel,
                             cudaFuncAttributeMaxDynamicSharedMemorySize, SMEM_REQ);
        attr_done = true;
    }

    transpose_kernel<<<dim3(LSEQ / 32, DIM / 32, BATCH), dim3(32, 8)>>>(inputs);
    codebook_gemm_kernel<<<dim3(DIM / 128, NUM_E / 128), 256>>>(emb, proj);
    rownorm_all_kernel<<<((NTOK + NUM_E) * 32) / 256, 256>>>();
    filter_kernel<<<(NTOK / 128) * 8, 512, SMEM_REQ>>>();   // 4th launch -> ncu slot
    rescore_kernel<<<NTOK / 256, 256>>>();
    gather_out_kernel<<<NTOK / 16, 256>>>(inputs, out);
    loss_final_kernel<<<1, 1>>>(out);
}

// round 14
// speedup vs baseline: 1.1132x; 1.1132x over previous
#include <cuda_runtime.h>
#include <cuda_fp16.h>
#include <math_constants.h>
#include <cstdint>

#define NUM_E 8192
#define DIM   512
#define BATCH 8
#define LSEQ  4096
#define NTOK  (BATCH * LSEQ)          // 32768
#define QELEMS ((size_t)BATCH * DIM * LSEQ)  // 16777216
#define CAP   256
#define TAU   8e-4f
#define CSCALE 8192.0f
#define NEG2S (-2.0f / 8192.0f)

// ---------------- scratch (device globals; no runtime allocation) ----------
__device__ __align__(256) float   g_xT[(size_t)NTOK * DIM];
__device__ __align__(256) __half  g_xhf[(size_t)NTOK * DIM];       // [N,D] fp16
__device__ __align__(256) float   g_codebook[(size_t)NUM_E * DIM];
__device__ __align__(256) __half2 g_chfT2[(size_t)DIM * NUM_E];    // [D,K] splat fp16*8192
__device__ float    g_xnorm[NTOK];
__device__ float    g_cnorm[NUM_E];
__device__ int      g_ck[(size_t)NTOK * CAP];    // candidate indices
__device__ float    g_cv[(size_t)NTOK * CAP];    // candidate fp16-filter scores
__device__ uint32_t g_fminu[NTOK];               // global fp16 min (fmap'd uint)
__device__ uint32_t g_cnt[NTOK];
__device__ int      g_argmin[NTOK];
__device__ double   g_loss;

// order-preserving float<->uint map for unsigned atomicMin
__device__ __forceinline__ uint32_t fmap(float f) {
    uint32_t u = __float_as_uint(f);
    return (u & 0x80000000u) ? ~u : (u | 0x80000000u);
}
__device__ __forceinline__ float funmap(uint32_t u) {
    return __uint_as_float((u & 0x80000000u) ? (u & 0x7FFFFFFFu) : ~u);
}
__device__ __forceinline__ uint32_t smem_u32(const void* p) {
    uint32_t a;
    asm("{ .reg .u64 t; cvta.to.shared.u64 t, %1; cvt.u32.u64 %0, t; }"
        : "=r"(a) : "l"(p));
    return a;
}
__device__ __forceinline__ void cp16(uint32_t dst, const void* src) {
    asm volatile("cp.async.cg.shared.global [%0], [%1], 16;" :: "r"(dst), "l"(src));
}
#define CP_COMMIT() asm volatile("cp.async.commit_group;" ::: "memory")
#define CP_WAIT0()  asm volatile("cp.async.wait_group 0;" ::: "memory")

// ---------------------------------------------------------------------------
// inputs [B, D, L] -> g_xT / g_xhf; first 128 blocks also init filter scratch
__global__ void transpose_kernel(const float* __restrict__ in) {
    __shared__ float tile[32][33];
    int b  = blockIdx.z;
    int d0 = blockIdx.y * 32;
    int l0 = blockIdx.x * 32;
    int tx = threadIdx.x, ty = threadIdx.y;
    int tid = ty * 32 + tx;
    int gid = (blockIdx.z * gridDim.y + blockIdx.y) * gridDim.x + blockIdx.x;
    if (gid < NTOK / 256) {
        int i = gid * 256 + tid;
        g_cnt[i] = 0u;
        g_fminu[i] = 0xFF800000u;   // fmap(+inf)
        if (i == 0) g_loss = 0.0;
    }
    const float* src = in + (size_t)b * DIM * LSEQ;
#pragma unroll
    for (int i = 0; i < 4; i++)
        tile[ty + i * 8][tx] = src[(size_t)(d0 + ty + i * 8) * LSEQ + l0 + tx];
    __syncthreads();
#pragma unroll
    for (int i = 0; i < 4; i++) {
        int l = l0 + ty + i * 8;
        float v = tile[tx][ty + i * 8];
        size_t idx = (size_t)(b * LSEQ + l) * DIM + d0 + tx;
        g_xT[idx] = v;
        g_xhf[idx] = __float2half(v);
    }
}

// codebook[k][d] = sum_j emb[k][j] * proj[d][j]  (128x128 tile, 8x8/thread)
// also writes transposed scaled SPLATTED fp16 copy g_chfT2[d][k] = (v,v)
__global__ __launch_bounds__(256, 2) void codebook_gemm_kernel(
    const float* __restrict__ E, const float* __restrict__ P) {
    __shared__ float As[8][128];
    __shared__ float Bs[8][128];
    int tid = threadIdx.x;
    int ty = tid >> 4, tx = tid & 15;
    int k0 = blockIdx.y * 128;
    int d0 = blockIdx.x * 128;
    int srow = tid >> 2;
    int scol = (tid & 3) * 2;
    float acc[8][8];
#pragma unroll
    for (int i = 0; i < 8; i++)
#pragma unroll
        for (int j = 0; j < 8; j++) acc[i][j] = 0.f;

    for (int j0 = 0; j0 < DIM; j0 += 8) {
#pragma unroll
        for (int i = 0; i < 2; i++) {
            int m = srow + i * 64;
            float2 av = *(const float2*)&E[(size_t)(k0 + m) * DIM + j0 + scol];
            float2 bv = *(const float2*)&P[(size_t)(d0 + m) * DIM + j0 + scol];
            As[scol][m] = av.x; As[scol + 1][m] = av.y;
            Bs[scol][m] = bv.x; Bs[scol + 1][m] = bv.y;
        }
        __syncthreads();
#pragma unroll
        for (int j = 0; j < 8; j++) {
            float a[8], bb[8];
#pragma unroll
            for (int i = 0; i < 8; i++) a[i]  = As[j][ty * 8 + i];
#pragma unroll
            for (int i = 0; i < 8; i++) bb[i] = Bs[j][tx * 8 + i];
#pragma unroll
            for (int i = 0; i < 8; i++)
#pragma unroll
                for (int jj = 0; jj < 8; jj++) acc[i][jj] += a[i] * bb[jj];
        }
        __syncthreads();
    }
#pragma unroll
    for (int i = 0; i < 8; i++)
#pragma unroll
        for (int jj = 0; jj < 8; jj++)
            g_codebook[(size_t)(k0 + ty * 8 + i) * DIM + d0 + tx * 8 + jj] = acc[i][jj];
#pragma unroll
    for (int jj = 0; jj < 8; jj++) {
        __half2 w[8];
#pragma unroll
        for (int i = 0; i < 8; i++)
            w[i] = __half2half2(__float2half(acc[i][jj] * CSCALE));
        __half2* dst = &g_chfT2[(size_t)(d0 + tx * 8 + jj) * NUM_E + k0 + ty * 8];
        *(uint4*)(dst)     = *(uint4*)&w[0];
        *(uint4*)(dst + 4) = *(uint4*)&w[4];
    }
}

// merged: warps [0, NTOK) -> xnorm rows; warps [NTOK, NTOK+NUM_E) -> cnorm
__global__ void rownorm_all_kernel() {
    int warp = (blockIdx.x * blockDim.x + threadIdx.x) >> 5;
    int lane = threadIdx.x & 31;
    if (warp >= NTOK + NUM_E) return;
    bool isc = warp >= NTOK;
    const float* r = isc ? (g_codebook + (size_t)(warp - NTOK) * DIM)
                         : (g_xT + (size_t)warp * DIM);
    float s = 0.f;
#pragma unroll
    for (int i = 0; i < DIM / 32; i++) { float v = r[lane + i * 32]; s += v * v; }
#pragma unroll
    for (int o = 16; o; o >>= 1) s += __shfl_down_sync(0xffffffffu, s, o);
    if (lane == 0) {
        if (isc) g_cnorm[warp - NTOK] = s;
        else     g_xnorm[warp] = s;
    }
}

// ------------------- fp16x2 (HFMA2) candidate-filter kernel ----------------
// 512 threads.  Grid: blockIdx.x = m_tile*4 + k_quarter.  CTA: 128 tokens x
// 2048 codes (8 tiles of 256).  Thread (ty 0..15, tx 0..31) = 4 token-pairs
// x 8 codes, acc[4][8] -> 32 HFMA2 per dim, 48B smem per dim (fat tile).
// Warp = fixed ty: X read is a conflict-free broadcast; code reads are
// contiguous 512B via de-interleave phys(u) = (u&1)*32 + (u>>1).
// Chunks of 32 dims x 256 codes (32KB), 2-buffer ring, depth-1 prefetch.
#define OFF_X    0                    // Xp2 [512][64] half2 = 131072
#define OFF_C    131072               // Cs [2][32][256] half2 = 65536
#define OFF_RMIN 196608               // 512
#define OFF_CNS  197120               // 1024 (256 floats)
#define OFF_THR  198144               // 512
#define SMEM_REQ 198656

__global__ __launch_bounds__(512, 1) void filter_kernel() {
    extern __shared__ __align__(16) char sm[];
    uint32_t smb = smem_u32(sm);
    int tid = threadIdx.x;
    int m0 = (blockIdx.x >> 2) * 128;
    int e4 = blockIdx.x & 3;           // k-quarter: codes [e4*2048, +2048)
    int ty = tid >> 5, tx = tid & 31;  // ty: 4 token-pairs; tx: 8 codes

    __half2*  Xp2    = (__half2*)(sm + OFF_X);     // [512][64]
    uint32_t  csmem  = smb + OFF_C;                // ring base (bytes)
    uint32_t* rmin_s = (uint32_t*)(sm + OFF_RMIN);
    float*    cn_s   = (float*)(sm + OFF_CNS);
    float*    thr_s  = (float*)(sm + OFF_THR);

    if (tid < 128) rmin_s[tid] = 0xFF800000u;      // fmap(+inf)

    // ---- build resident Xp2[d][tp] = (x[2tp][d], x[2tp+1][d]) ----
    {
        int tp = tid & 63;
        int dh = (tid >> 6) * 64;    // 8 groups x 64 dims
        const uint4* x0 = (const uint4*)(g_xhf + (size_t)(m0 + 2 * tp) * DIM + dh);
        const uint4* x1 = (const uint4*)(g_xhf + (size_t)(m0 + 2 * tp + 1) * DIM + dh);
#pragma unroll 4
        for (int v = 0; v < 8; v++) {
            uint4 q0 = x0[v];
            uint4 q1 = x1[v];
            const __half* h0 = (const __half*)&q0;
            const __half* h1 = (const __half*)&q1;
#pragma unroll
            for (int u = 0; u < 8; u++)
                Xp2[(size_t)(dh + v * 8 + u) * 64 + tp] = __halves2half2(h0[u], h1[u]);
        }
    }

    __half2 acc[4][8];
    const __half2 hz = __float2half2_rn(0.f);
#pragma unroll
    for (int i = 0; i < 4; i++)
#pragma unroll
        for (int p = 0; p < 8; p++) acc[i][p] = hz;

    // cp.async staging: chunk = 32 rows x 64 units(16B); thread: 4 units
    int crow = tid >> 4;               // 0..31 (dim row within chunk)
    int uu   = tid & 15;               // units uu, uu+16, uu+32, uu+48
    auto issue = [&](int t) {
        if (t < 128) {
            int buf = t & 1;
            const __half2* srow = g_chfT2
                + (size_t)((t & 15) * 32 + crow) * NUM_E
                + e4 * 2048 + (t >> 4) * 256;
            uint32_t drow = csmem + (uint32_t)buf * 32768 + (uint32_t)crow * 1024;
#pragma unroll
            for (int i = 0; i < 4; i++) {
                int u = uu + i * 16;                      // logical 16B unit
                uint32_t phys = (uint32_t)(((u & 1) << 5) + (u >> 1)) * 16;
                cp16(drow + phys, srow + u * 4);
            }
        }
        CP_COMMIT();
    };

    // compute one 32-dim chunk from ring buffer buf
    auto compute_chunk = [&](int t, int buf) {
        int c = t & 15;
        const __half2* xb = Xp2 + (size_t)(c * 32) * 64 + ty * 4;
        const char* cbp = (const char*)sm + OFF_C + buf * 32768 + tx * 16;
#pragma unroll 8
        for (int j = 0; j < 32; j++) {
            uint4 xq = *(const uint4*)(xb + (size_t)j * 64);   // broadcast in warp
            __half2 xv[4];
            xv[0] = *(__half2*)&xq.x; xv[1] = *(__half2*)&xq.y;
            xv[2] = *(__half2*)&xq.z; xv[3] = *(__half2*)&xq.w;
            uint4 cq0 = *(const uint4*)(cbp + j * 1024);        // codes 8tx..+3
            uint4 cq1 = *(const uint4*)(cbp + j * 1024 + 512);  // codes 8tx+4..+7
            __half2 cv[8];
            cv[0] = *(__half2*)&cq0.x; cv[1] = *(__half2*)&cq0.y;
            cv[2] = *(__half2*)&cq0.z; cv[3] = *(__half2*)&cq0.w;
            cv[4] = *(__half2*)&cq1.x; cv[5] = *(__half2*)&cq1.y;
            cv[6] = *(__half2*)&cq1.z; cv[7] = *(__half2*)&cq1.w;
#pragma unroll
            for (int i = 0; i < 4; i++)
#pragma unroll
                for (int p = 0; p < 8; p++)
                    acc[i][p] = __hfma2(xv[i], cv[p], acc[i][p]);
        }
    };

    issue(0);

    for (int t = 0; t < 128; t++) {    // 8 tiles x 16 chunks(32 dims)
        CP_WAIT0();                    // chunk t landed
        __syncthreads();               // reads of other buffer complete
        issue(t + 1);                  // prefetch into other buffer
        if ((t & 15) == 0 && tid < 256)
            cn_s[tid] = __ldg(&g_cnorm[e4 * 2048 + (t >> 4) * 256 + tid]);

        compute_chunk(t, t & 1);

        if ((t & 15) == 15) {
            int k0 = e4 * 2048 + (t >> 4) * 256;
            // ---- Phase A: per-token TILE min into rmin_s ----
#pragma unroll
            for (int i = 0; i < 4; i++) {
                float lm0 = CUDART_INF_F, lm1 = CUDART_INF_F;
#pragma unroll
                for (int p = 0; p < 8; p++) {
                    float2 f = __half22float2(acc[i][p]);
                    float cn = cn_s[tx * 8 + p];
                    lm0 = fminf(lm0, fmaf(f.x, NEG2S, cn));
                    lm1 = fminf(lm1, fmaf(f.y, NEG2S, cn));
                }
                atomicMin(&rmin_s[ty * 8 + 2 * i],     fmap(lm0));
                atomicMin(&rmin_s[ty * 8 + 2 * i + 1], fmap(lm1));
            }
            __syncthreads();
            // ---- merge tile min into GLOBAL min; threshold = merged + TAU
            if (tid < 128) {
                uint32_t tm  = rmin_s[tid];
                uint32_t old = atomicMin(&g_fminu[m0 + tid], tm);
                thr_s[tid] = funmap(old < tm ? old : tm) + TAU;
                rmin_s[tid] = 0xFF800000u;   // reset for next tile
            }
            __syncthreads();
            // ---- Phase B: append (k, sv) to GLOBAL within threshold ----
#pragma unroll
            for (int i = 0; i < 4; i++) {
                int r0 = ty * 8 + 2 * i, r1 = r0 + 1;
                float thr0 = thr_s[r0];
                float thr1 = thr_s[r1];
#pragma unroll
                for (int p = 0; p < 8; p++) {
                    float2 f = __half22float2(acc[i][p]);
                    float cn = cn_s[tx * 8 + p];
                    float s0 = fmaf(f.x, NEG2S, cn);
                    float s1 = fmaf(f.y, NEG2S, cn);
                    int kk = k0 + tx * 8 + p;
                    if (s0 <= thr0) {
                        uint32_t slot = atomicAdd(&g_cnt[m0 + r0], 1u);
                        if (slot < CAP) {
                            g_ck[(size_t)(m0 + r0) * CAP + slot] = kk;
                            g_cv[(size_t)(m0 + r0) * CAP + slot] = s0;
                        }
                    }
                    if (s1 <= thr1) {
                        uint32_t slot = atomicAdd(&g_cnt[m0 + r1], 1u);
                        if (slot < CAP) {
                            g_ck[(size_t)(m0 + r1) * CAP + slot] = kk;
                            g_cv[(size_t)(m0 + r1) * CAP + slot] = s1;
                        }
                    }
                    acc[i][p] = hz;
                }
            }
        }
    }
}

// exact fp32 rescore; pre-filter candidates by final global-min window.
// count > CAP => full-scan fallback (P ~ 0 with CAP=256)
__global__ __launch_bounds__(256) void rescore_kernel() {
    int t = blockIdx.x * 256 + threadIdx.x;
    float xn = g_xnorm[t];
    uint32_t n = g_cnt[t];
    float thr = funmap(g_fminu[t]) + TAU;
    const float4* xr = (const float4*)(g_xT + (size_t)t * DIM);
    float best = CUDART_INF_F;
    int bi = 0;
    bool fb = (n > CAP);
    int total = fb ? NUM_E : (int)n;
    for (int i = 0; i < total; i++) {
        int k;
        if (fb) {
            k = i;
        } else {
            if (g_cv[(size_t)t * CAP + i] > thr) continue;  // outside final window
            k = g_ck[(size_t)t * CAP + i];
        }
        const float4* cr = (const float4*)(g_codebook + (size_t)k * DIM);
        float acc = 0.f;
#pragma unroll 8
        for (int v = 0; v < DIM / 4; v++) {
            float4 a = xr[v], b = cr[v];
            acc = fmaf(a.x, b.x, acc);
            acc = fmaf(a.y, b.y, acc);
            acc = fmaf(a.z, b.z, acc);
            acc = fmaf(a.w, b.w, acc);
        }
        float dv = (xn + g_cnorm[k]) - 2.0f * acc;
        if (dv < best || (dv == best && k < bi)) { best = dv; bi = k; }
    }
    g_argmin[t] = bi;
}

// gather codebook rows, write quantized [B,D,L], indices-as-float, loss accum
__global__ __launch_bounds__(256) void gather_out_kernel(
    const float* __restrict__ in, float* __restrict__ out) {
    __shared__ float qs[16][513];
    __shared__ int sidx[16];
    __shared__ double wsum[8];
    int t0 = blockIdx.x * 16;
    int tid = threadIdx.x;
    if (tid < 16) sidx[tid] = g_argmin[t0 + tid];
    __syncthreads();
#pragma unroll
    for (int i = 0; i < 8; i++) {
        int e = tid + i * 256;
        int tok = e >> 7, d4 = e & 127;
        float4 v = *(const float4*)&g_codebook[(size_t)sidx[tok] * DIM + d4 * 4];
        qs[tok][d4 * 4]     = v.x;
        qs[tok][d4 * 4 + 1] = v.y;
        qs[tok][d4 * 4 + 2] = v.z;
        qs[tok][d4 * 4 + 3] = v.w;
    }
    __syncthreads();
    int b  = t0 / LSEQ;
    int l0 = t0 % LSEQ;
    const float* src = in  + (size_t)b * DIM * LSEQ;
    float*       dst = out + (size_t)b * DIM * LSEQ;
    double ls = 0.0;
#pragma unroll
    for (int i = 0; i < 32; i++) {
        int e = tid + i * 256;
        int d = e >> 4, l = e & 15;
        float q = qs[l][d];
        float x = src[(size_t)d * LSEQ + l0 + l];
        float dd = q - x;
        dst[(size_t)d * LSEQ + l0 + l] = x + dd;
        ls += (double)dd * (double)dd;
    }
    if (tid < 16) out[QELEMS + 1 + (size_t)(t0 + tid)] = (float)sidx[tid];
#pragma unroll
    for (int o = 16; o; o >>= 1) ls += __shfl_down_sync(0xffffffffu, ls, o);
    if ((tid & 31) == 0) wsum[tid >> 5] = ls;
    __syncthreads();
    if (tid == 0) {
        double s = 0.0;
#pragma unroll
        for (int w = 0; w < 8; w++) s += wsum[w];
        atomicAdd(&g_loss, s);
    }
}

__global__ void loss_final_kernel(float* __restrict__ out) {
    out[QELEMS] = (float)(1.25 * g_loss / (double)QELEMS);
}

// ---------------------------------------------------------------------------
extern "C" void kernel_launch(void* const* d_in, const int* in_sizes, int n_in,
                              void* d_out, int out_size) {
    const float* inputs = (const float*)d_in[0];
    const float* emb    = (const float*)d_in[1];
    const float* proj   = (const float*)d_in[2];
    float* out = (float*)d_out;

    static bool attr_done = false;
    if (!attr_done) {
        cudaFuncSetAttribute(filter_kernel,
                             cudaFuncAttributeMaxDynamicSharedMemorySize, SMEM_REQ);
        attr_done = true;
    }

    transpose_kernel<<<dim3(LSEQ / 32, DIM / 32, BATCH), dim3(32, 8)>>>(inputs);
    codebook_gemm_kernel<<<dim3(DIM / 128, NUM_E / 128), 256>>>(emb, proj);
    rownorm_all_kernel<<<((NTOK + NUM_E) * 32) / 256, 256>>>();
    filter_kernel<<<(NTOK / 128) * 4, 512, SMEM_REQ>>>();   // 4th launch -> ncu slot
    rescore_kernel<<<NTOK / 256, 256>>>();
    gather_out_kernel<<<NTOK / 16, 256>>>(inputs, out);
    loss_final_kernel<<<1, 1>>>(out);
}

// round 15
// speedup vs baseline: 1.1392x; 1.0233x over previous
#include <cuda_runtime.h>
#include <cuda_fp16.h>
#include <math_constants.h>
#include <cstdint>

#define NUM_E 8192
#define DIM   512
#define BATCH 8
#define LSEQ  4096
#define NTOK  (BATCH * LSEQ)          // 32768
#define QELEMS ((size_t)BATCH * DIM * LSEQ)  // 16777216
#define CAP   256
#define TAU   8e-4f
#define CSCALE 8192.0f
#define NEG2S (-2.0f / 8192.0f)

// ---------------- scratch (device globals; no runtime allocation) ----------
__device__ __align__(256) float   g_xT[(size_t)NTOK * DIM];
__device__ __align__(256) __half  g_xhf[(size_t)NTOK * DIM];       // [N,D] fp16
__device__ __align__(256) float   g_codebook[(size_t)NUM_E * DIM];
__device__ __align__(256) __half2 g_chfT2[(size_t)DIM * NUM_E];    // [D,K] splat fp16*8192
__device__ float    g_xnorm[NTOK];
__device__ float    g_cnorm[NUM_E];
__device__ int      g_ck[(size_t)NTOK * CAP];    // candidate indices
__device__ float    g_cv[(size_t)NTOK * CAP];    // candidate fp16-filter scores
__device__ uint32_t g_fminu[NTOK];               // global fp16 min (fmap'd uint)
__device__ uint32_t g_cnt[NTOK];
__device__ int      g_argmin[NTOK];
__device__ double   g_loss;

// order-preserving float<->uint map for unsigned atomicMin
__device__ __forceinline__ uint32_t fmap(float f) {
    uint32_t u = __float_as_uint(f);
    return (u & 0x80000000u) ? ~u : (u | 0x80000000u);
}
__device__ __forceinline__ float funmap(uint32_t u) {
    return __uint_as_float((u & 0x80000000u) ? (u & 0x7FFFFFFFu) : ~u);
}
__device__ __forceinline__ uint32_t smem_u32(const void* p) {
    uint32_t a;
    asm("{ .reg .u64 t; cvta.to.shared.u64 t, %1; cvt.u32.u64 %0, t; }"
        : "=r"(a) : "l"(p));
    return a;
}
__device__ __forceinline__ void cp16(uint32_t dst, const void* src) {
    asm volatile("cp.async.cg.shared.global [%0], [%1], 16;" :: "r"(dst), "l"(src));
}
#define CP_COMMIT() asm volatile("cp.async.commit_group;" ::: "memory")
#define CP_WAIT0()  asm volatile("cp.async.wait_group 0;" ::: "memory")

// ---------------------------------------------------------------------------
// inputs [B, D, L] -> g_xT / g_xhf; first 128 blocks also init filter scratch
__global__ void transpose_kernel(const float* __restrict__ in) {
    __shared__ float tile[32][33];
    int b  = blockIdx.z;
    int d0 = blockIdx.y * 32;
    int l0 = blockIdx.x * 32;
    int tx = threadIdx.x, ty = threadIdx.y;
    int tid = ty * 32 + tx;
    int gid = (blockIdx.z * gridDim.y + blockIdx.y) * gridDim.x + blockIdx.x;
    if (gid < NTOK / 256) {
        int i = gid * 256 + tid;
        g_cnt[i] = 0u;
        g_fminu[i] = 0xFF800000u;   // fmap(+inf)
        if (i == 0) g_loss = 0.0;
    }
    const float* src = in + (size_t)b * DIM * LSEQ;
#pragma unroll
    for (int i = 0; i < 4; i++)
        tile[ty + i * 8][tx] = src[(size_t)(d0 + ty + i * 8) * LSEQ + l0 + tx];
    __syncthreads();
#pragma unroll
    for (int i = 0; i < 4; i++) {
        int l = l0 + ty + i * 8;
        float v = tile[tx][ty + i * 8];
        size_t idx = (size_t)(b * LSEQ + l) * DIM + d0 + tx;
        g_xT[idx] = v;
        g_xhf[idx] = __float2half(v);
    }
}

// codebook[k][d] = sum_j emb[k][j] * proj[d][j]  (128x128 tile, 8x8/thread)
// also writes transposed scaled SPLATTED fp16 copy g_chfT2[d][k] = (v,v)
__global__ __launch_bounds__(256, 2) void codebook_gemm_kernel(
    const float* __restrict__ E, const float* __restrict__ P) {
    __shared__ float As[8][128];
    __shared__ float Bs[8][128];
    int tid = threadIdx.x;
    int ty = tid >> 4, tx = tid & 15;
    int k0 = blockIdx.y * 128;
    int d0 = blockIdx.x * 128;
    int srow = tid >> 2;
    int scol = (tid & 3) * 2;
    float acc[8][8];
#pragma unroll
    for (int i = 0; i < 8; i++)
#pragma unroll
        for (int j = 0; j < 8; j++) acc[i][j] = 0.f;

    for (int j0 = 0; j0 < DIM; j0 += 8) {
#pragma unroll
        for (int i = 0; i < 2; i++) {
            int m = srow + i * 64;
            float2 av = *(const float2*)&E[(size_t)(k0 + m) * DIM + j0 + scol];
            float2 bv = *(const float2*)&P[(size_t)(d0 + m) * DIM + j0 + scol];
            As[scol][m] = av.x; As[scol + 1][m] = av.y;
            Bs[scol][m] = bv.x; Bs[scol + 1][m] = bv.y;
        }
        __syncthreads();
#pragma unroll
        for (int j = 0; j < 8; j++) {
            float a[8], bb[8];
#pragma unroll
            for (int i = 0; i < 8; i++) a[i]  = As[j][ty * 8 + i];
#pragma unroll
            for (int i = 0; i < 8; i++) bb[i] = Bs[j][tx * 8 + i];
#pragma unroll
            for (int i = 0; i < 8; i++)
#pragma unroll
                for (int jj = 0; jj < 8; jj++) acc[i][jj] += a[i] * bb[jj];
        }
        __syncthreads();
    }
#pragma unroll
    for (int i = 0; i < 8; i++)
#pragma unroll
        for (int jj = 0; jj < 8; jj++)
            g_codebook[(size_t)(k0 + ty * 8 + i) * DIM + d0 + tx * 8 + jj] = acc[i][jj];
#pragma unroll
    for (int jj = 0; jj < 8; jj++) {
        __half2 w[8];
#pragma unroll
        for (int i = 0; i < 8; i++)
            w[i] = __half2half2(__float2half(acc[i][jj] * CSCALE));
        __half2* dst = &g_chfT2[(size_t)(d0 + tx * 8 + jj) * NUM_E + k0 + ty * 8];
        *(uint4*)(dst)     = *(uint4*)&w[0];
        *(uint4*)(dst + 4) = *(uint4*)&w[4];
    }
}

// merged: warps [0, NTOK) -> xnorm rows; warps [NTOK, NTOK+NUM_E) -> cnorm
__global__ void rownorm_all_kernel() {
    int warp = (blockIdx.x * blockDim.x + threadIdx.x) >> 5;
    int lane = threadIdx.x & 31;
    if (warp >= NTOK + NUM_E) return;
    bool isc = warp >= NTOK;
    const float* r = isc ? (g_codebook + (size_t)(warp - NTOK) * DIM)
                         : (g_xT + (size_t)warp * DIM);
    float s = 0.f;
#pragma unroll
    for (int i = 0; i < DIM / 32; i++) { float v = r[lane + i * 32]; s += v * v; }
#pragma unroll
    for (int o = 16; o; o >>= 1) s += __shfl_down_sync(0xffffffffu, s, o);
    if (lane == 0) {
        if (isc) g_cnorm[warp - NTOK] = s;
        else     g_xnorm[warp] = s;
    }
}

// ------------------- fp16x2 (HFMA2) candidate-filter kernel ----------------
// 512 threads.  Grid: blockIdx.x = m_tile*4 + k_quarter.  CTA: 128 tokens x
// 2048 codes (8 tiles of 256).  Thread (ty 0..15, tx 0..31) = 4 token-pairs
// x 8 codes, acc[4][8].  Epilogue: warp REDUX tile-min (no smem atomics) +
// warp-uniform Phase-B skip via tmin_s vs thr_s.
#define OFF_X    0                    // Xp2 [512][64] half2 = 131072
#define OFF_C    131072               // Cs [2][32][256] half2 = 65536
#define OFF_RMIN 196608               // 512
#define OFF_CNS  197120               // 1024 (256 floats)
#define OFF_THR  198144               // 512
#define OFF_TMIN 198656               // 512
#define SMEM_REQ 199168

__global__ __launch_bounds__(512, 1) void filter_kernel() {
    extern __shared__ __align__(16) char sm[];
    uint32_t smb = smem_u32(sm);
    int tid = threadIdx.x;
    int m0 = (blockIdx.x >> 2) * 128;
    int e4 = blockIdx.x & 3;           // k-quarter: codes [e4*2048, +2048)
    int ty = tid >> 5, tx = tid & 31;  // ty: 4 token-pairs; tx: 8 codes

    __half2*  Xp2    = (__half2*)(sm + OFF_X);     // [512][64]
    uint32_t  csmem  = smb + OFF_C;                // ring base (bytes)
    uint32_t* rmin_s = (uint32_t*)(sm + OFF_RMIN);
    float*    cn_s   = (float*)(sm + OFF_CNS);
    float*    thr_s  = (float*)(sm + OFF_THR);
    float*    tmin_s = (float*)(sm + OFF_TMIN);

    // ---- build resident Xp2[d][tp] = (x[2tp][d], x[2tp+1][d]) ----
    {
        int tp = tid & 63;
        int dh = (tid >> 6) * 64;    // 8 groups x 64 dims
        const uint4* x0 = (const uint4*)(g_xhf + (size_t)(m0 + 2 * tp) * DIM + dh);
        const uint4* x1 = (const uint4*)(g_xhf + (size_t)(m0 + 2 * tp + 1) * DIM + dh);
#pragma unroll 4
        for (int v = 0; v < 8; v++) {
            uint4 q0 = x0[v];
            uint4 q1 = x1[v];
            const __half* h0 = (const __half*)&q0;
            const __half* h1 = (const __half*)&q1;
#pragma unroll
            for (int u = 0; u < 8; u++)
                Xp2[(size_t)(dh + v * 8 + u) * 64 + tp] = __halves2half2(h0[u], h1[u]);
        }
    }

    __half2 acc[4][8];
    const __half2 hz = __float2half2_rn(0.f);
#pragma unroll
    for (int i = 0; i < 4; i++)
#pragma unroll
        for (int p = 0; p < 8; p++) acc[i][p] = hz;

    // cp.async staging: chunk = 32 rows x 64 units(16B); thread: 4 units
    int crow = tid >> 4;               // 0..31 (dim row within chunk)
    int uu   = tid & 15;               // units uu, uu+16, uu+32, uu+48
    auto issue = [&](int t) {
        if (t < 128) {
            int buf = t & 1;
            const __half2* srow = g_chfT2
                + (size_t)((t & 15) * 32 + crow) * NUM_E
                + e4 * 2048 + (t >> 4) * 256;
            uint32_t drow = csmem + (uint32_t)buf * 32768 + (uint32_t)crow * 1024;
#pragma unroll
            for (int i = 0; i < 4; i++) {
                int u = uu + i * 16;                      // logical 16B unit
                uint32_t phys = (uint32_t)(((u & 1) << 5) + (u >> 1)) * 16;
                cp16(drow + phys, srow + u * 4);
            }
        }
        CP_COMMIT();
    };

    // compute one 32-dim chunk from ring buffer buf
    auto compute_chunk = [&](int t, int buf) {
        int c = t & 15;
        const __half2* xb = Xp2 + (size_t)(c * 32) * 64 + ty * 4;
        const char* cbp = (const char*)sm + OFF_C + buf * 32768 + tx * 16;
#pragma unroll 8
        for (int j = 0; j < 32; j++) {
            uint4 xq = *(const uint4*)(xb + (size_t)j * 64);   // broadcast in warp
            __half2 xv[4];
            xv[0] = *(__half2*)&xq.x; xv[1] = *(__half2*)&xq.y;
            xv[2] = *(__half2*)&xq.z; xv[3] = *(__half2*)&xq.w;
            uint4 cq0 = *(const uint4*)(cbp + j * 1024);        // codes 8tx..+3
            uint4 cq1 = *(const uint4*)(cbp + j * 1024 + 512);  // codes 8tx+4..+7
            __half2 cv[8];
            cv[0] = *(__half2*)&cq0.x; cv[1] = *(__half2*)&cq0.y;
            cv[2] = *(__half2*)&cq0.z; cv[3] = *(__half2*)&cq0.w;
            cv[4] = *(__half2*)&cq1.x; cv[5] = *(__half2*)&cq1.y;
            cv[6] = *(__half2*)&cq1.z; cv[7] = *(__half2*)&cq1.w;
#pragma unroll
            for (int i = 0; i < 4; i++)
#pragma unroll
                for (int p = 0; p < 8; p++)
                    acc[i][p] = __hfma2(xv[i], cv[p], acc[i][p]);
        }
    };

    issue(0);
    __syncthreads();   // Xp2 visible before first compute

    for (int t = 0; t < 128; t++) {    // 8 tiles x 16 chunks(32 dims)
        CP_WAIT0();                    // chunk t landed
        __syncthreads();               // reads of other buffer complete
        issue(t + 1);                  // prefetch into other buffer
        if ((t & 15) == 0 && tid < 256)
            cn_s[tid] = __ldg(&g_cnorm[e4 * 2048 + (t >> 4) * 256 + tid]);

        compute_chunk(t, t & 1);

        if ((t & 15) == 15) {
            int k0 = e4 * 2048 + (t >> 4) * 256;
            // ---- Phase A: warp-reduced tile min per token, lane-0 store ----
#pragma unroll
            for (int i = 0; i < 4; i++) {
                float lm0 = CUDART_INF_F, lm1 = CUDART_INF_F;
#pragma unroll
                for (int p = 0; p < 8; p++) {
                    float2 f = __half22float2(acc[i][p]);
                    float cn = cn_s[tx * 8 + p];
                    lm0 = fminf(lm0, fmaf(f.x, NEG2S, cn));
                    lm1 = fminf(lm1, fmaf(f.y, NEG2S, cn));
                }
                uint32_t w0 = __reduce_min_sync(0xffffffffu, fmap(lm0));
                uint32_t w1 = __reduce_min_sync(0xffffffffu, fmap(lm1));
                if (tx == 0) {
                    rmin_s[ty * 8 + 2 * i]     = w0;   // warp owns these tokens
                    rmin_s[ty * 8 + 2 * i + 1] = w1;
                }
            }
            __syncthreads();
            // ---- merge tile min into GLOBAL min; threshold = merged + TAU
            if (tid < 128) {
                uint32_t tm  = rmin_s[tid];
                uint32_t old = atomicMin(&g_fminu[m0 + tid], tm);
                thr_s[tid]  = funmap(old < tm ? old : tm) + TAU;
                tmin_s[tid] = funmap(tm);
            }
            __syncthreads();
            // ---- Phase B: append only if tile can contain a candidate ----
#pragma unroll
            for (int i = 0; i < 4; i++) {
                int r0 = ty * 8 + 2 * i, r1 = r0 + 1;
                float thr0 = thr_s[r0];
                float thr1 = thr_s[r1];
                bool do0 = tmin_s[r0] <= thr0;   // warp-uniform
                bool do1 = tmin_s[r1] <= thr1;
                if (do0 || do1) {
#pragma unroll
                    for (int p = 0; p < 8; p++) {
                        float2 f = __half22float2(acc[i][p]);
                        float cn = cn_s[tx * 8 + p];
                        float s0 = fmaf(f.x, NEG2S, cn);
                        float s1 = fmaf(f.y, NEG2S, cn);
                        int kk = k0 + tx * 8 + p;
                        if (do0 && s0 <= thr0) {
                            uint32_t slot = atomicAdd(&g_cnt[m0 + r0], 1u);
                            if (slot < CAP) {
                                g_ck[(size_t)(m0 + r0) * CAP + slot] = kk;
                                g_cv[(size_t)(m0 + r0) * CAP + slot] = s0;
                            }
                        }
                        if (do1 && s1 <= thr1) {
                            uint32_t slot = atomicAdd(&g_cnt[m0 + r1], 1u);
                            if (slot < CAP) {
                                g_ck[(size_t)(m0 + r1) * CAP + slot] = kk;
                                g_cv[(size_t)(m0 + r1) * CAP + slot] = s1;
                            }
                        }
                    }
                }
#pragma unroll
                for (int p = 0; p < 8; p++) acc[i][p] = hz;   // reset always
            }
        }
    }
}

// exact fp32 rescore; pre-filter candidates by final global-min window.
// count > CAP => full-scan fallback (P ~ 0 with CAP=256)
__global__ __launch_bounds__(256) void rescore_kernel() {
    int t = blockIdx.x * 256 + threadIdx.x;
    float xn = g_xnorm[t];
    uint32_t n = g_cnt[t];
    float thr = funmap(g_fminu[t]) + TAU;
    const float4* xr = (const float4*)(g_xT + (size_t)t * DIM);
    float best = CUDART_INF_F;
    int bi = 0;
    bool fb = (n > CAP);
    int total = fb ? NUM_E : (int)n;
    for (int i = 0; i < total; i++) {
        int k;
        if (fb) {
            k = i;
        } else {
            if (g_cv[(size_t)t * CAP + i] > thr) continue;  // outside final window
            k = g_ck[(size_t)t * CAP + i];
        }
        const float4* cr = (const float4*)(g_codebook + (size_t)k * DIM);
        float acc = 0.f;
#pragma unroll 8
        for (int v = 0; v < DIM / 4; v++) {
            float4 a = xr[v], b = cr[v];
            acc = fmaf(a.x, b.x, acc);
            acc = fmaf(a.y, b.y, acc);
            acc = fmaf(a.z, b.z, acc);
            acc = fmaf(a.w, b.w, acc);
        }
        float dv = (xn + g_cnorm[k]) - 2.0f * acc;
        if (dv < best || (dv == best && k < bi)) { best = dv; bi = k; }
    }
    g_argmin[t] = bi;
}

// gather codebook rows, write quantized [B,D,L], indices-as-float, loss accum
__global__ __launch_bounds__(256) void gather_out_kernel(
    const float* __restrict__ in, float* __restrict__ out) {
    __shared__ float qs[16][513];
    __shared__ int sidx[16];
    __shared__ double wsum[8];
    int t0 = blockIdx.x * 16;
    int tid = threadIdx.x;
    if (tid < 16) sidx[tid] = g_argmin[t0 + tid];
    __syncthreads();
#pragma unroll
    for (int i = 0; i < 8; i++) {
        int e = tid + i * 256;
        int tok = e >> 7, d4 = e & 127;
        float4 v = *(const float4*)&g_codebook[(size_t)sidx[tok] * DIM + d4 * 4];
        qs[tok][d4 * 4]     = v.x;
        qs[tok][d4 * 4 + 1] = v.y;
        qs[tok][d4 * 4 + 2] = v.z;
        qs[tok][d4 * 4 + 3] = v.w;
    }
    __syncthreads();
    int b  = t0 / LSEQ;
    int l0 = t0 % LSEQ;
    const float* src = in  + (size_t)b * DIM * LSEQ;
    float*       dst = out + (size_t)b * DIM * LSEQ;
    double ls = 0.0;
#pragma unroll
    for (int i = 0; i < 32; i++) {
        int e = tid + i * 256;
        int d = e >> 4, l = e & 15;
        float q = qs[l][d];
        float x = src[(size_t)d * LSEQ + l0 + l];
        float dd = q - x;
        dst[(size_t)d * LSEQ + l0 + l] = x + dd;
        ls += (double)dd * (double)dd;
    }
    if (tid < 16) out[QELEMS + 1 + (size_t)(t0 + tid)] = (float)sidx[tid];
#pragma unroll
    for (int o = 16; o; o >>= 1) ls += __shfl_down_sync(0xffffffffu, ls, o);
    if ((tid & 31) == 0) wsum[tid >> 5] = ls;
    __syncthreads();
    if (tid == 0) {
        double s = 0.0;
#pragma unroll
        for (int w = 0; w < 8; w++) s += wsum[w];
        atomicAdd(&g_loss, s);
    }
}

__global__ void loss_final_kernel(float* __restrict__ out) {
    out[QELEMS] = (float)(1.25 * g_loss / (double)QELEMS);
}

// ---------------------------------------------------------------------------
extern "C" void kernel_launch(void* const* d_in, const int* in_sizes, int n_in,
                              void* d_out, int out_size) {
    const float* inputs = (const float*)d_in[0];
    const float* emb    = (const float*)d_in[1];
    const float* proj   = (const float*)d_in[2];
    float* out = (float*)d_out;

    static bool attr_done = false;
    if (!attr_done) {
        cudaFuncSetAttribute(filter_kernel,
                             cudaFuncAttributeMaxDynamicSharedMemorySize, SMEM_REQ);
        attr_done = true;
    }

    transpose_kernel<<<dim3(LSEQ / 32, DIM / 32, BATCH), dim3(32, 8)>>>(inputs);
    codebook_gemm_kernel<<<dim3(DIM / 128, NUM_E / 128), 256>>>(emb, proj);
    rownorm_all_kernel<<<((NTOK + NUM_E) * 32) / 256, 256>>>();
    filter_kernel<<<(NTOK / 128) * 4, 512, SMEM_REQ>>>();   // 4th launch -> ncu slot
    rescore_kernel<<<NTOK / 256, 256>>>();
    gather_out_kernel<<<NTOK / 16, 256>>>(inputs, out);
    loss_final_kernel<<<1, 1>>>(out);
}